// round 4
// baseline (speedup 1.0000x reference)
#include <cuda_runtime.h>
#include <cuda_bf16.h>
#include <cstdint>

// Problem dims
#define TT 2048
#define BB 64
#define FFD 256
#define HH 256
#define NG 768  // 3*H

// Recurrence grid config
#define NBG 8      // batch groups
#define NCG 16     // col groups
#define BPG 8      // batches per group
#define NCTA 128   // NBG*NCG
#define NT 384     // threads per CTA

// -------- device scratch (static allocation is allowed) --------
__device__ float g_xi[(size_t)TT * BB * NG];     // 2048*64*768
__device__ float g_hT2[2 * HH * BB];             // double-buffered h, transposed [j][b]
__device__ unsigned g_bar[TT];                   // per-step barrier counters
__device__ float g_dump[(size_t)TT * BB * HH];   // fallback ys sink

// -------- packed f32x2 helpers --------
__device__ __forceinline__ void ffma2(unsigned long long& d, unsigned long long a, unsigned long long b) {
    asm volatile("fma.rn.f32x2 %0, %1, %2, %0;" : "+l"(d) : "l"(a), "l"(b));
}
__device__ __forceinline__ unsigned long long dup2(float a) {
    unsigned long long d;
    asm("mov.b64 %0, {%1, %1};" : "=l"(d) : "f"(a));
    return d;
}
__device__ __forceinline__ float2 unpack2(unsigned long long d) {
    float2 f;
    asm("mov.b64 {%0, %1}, %2;" : "=f"(f.x), "=f"(f.y) : "l"(d));
    return f;
}
__device__ __forceinline__ float tanh_ap(float x) {
    float y;
    asm("tanh.approx.f32 %0, %1;" : "=f"(y) : "f"(x));
    return y;
}
__device__ __forceinline__ float sigmoid_ap(float x) {
    return 0.5f * tanh_ap(0.5f * x) + 0.5f;
}

// ============================================================
// Kernel 0: zero barrier counters (must run before recurrence)
// ============================================================
__global__ void zero_bar_kernel() {
    int i = blockIdx.x * blockDim.x + threadIdx.x;
    if (i < TT) g_bar[i] = 0u;
}

// ============================================================
// Kernel 1: xi = xs @ Wi   (M=131072, K=256, N=768)
// 128x128 tiles, BK=16, 256 threads, 8x8 micro-tile, FFMA2.
// ============================================================
__global__ __launch_bounds__(256, 2) void gemm_xi_kernel(const float* __restrict__ A,
                                                         const float* __restrict__ W) {
    __shared__ float As[16][132];  // [k][m] padded
    __shared__ float Bs[16][128];  // [k][n]
    const int tid = threadIdx.x;
    const int m0 = blockIdx.y * 128;
    const int n0 = blockIdx.x * 128;
    const int nt = tid & 15;
    const int mt = tid >> 4;

    unsigned long long acc[8][4];
#pragma unroll
    for (int i = 0; i < 8; i++)
#pragma unroll
        for (int j = 0; j < 4; j++) acc[i][j] = 0ULL;

    for (int kt = 0; kt < 256; kt += 16) {
#pragma unroll
        for (int i = 0; i < 2; i++) {  // A tile: 512 float4
            int f4 = tid + i * 256;
            int row = f4 >> 2;
            int kq = (f4 & 3) << 2;
            float4 v = *(const float4*)(A + (size_t)(m0 + row) * 256 + kt + kq);
            As[kq + 0][row] = v.x; As[kq + 1][row] = v.y;
            As[kq + 2][row] = v.z; As[kq + 3][row] = v.w;
        }
#pragma unroll
        for (int i = 0; i < 2; i++) {  // B tile: 512 float4
            int f4 = tid + i * 256;
            int row = f4 >> 5;
            int nq = (f4 & 31) << 2;
            float4 v = *(const float4*)(W + (size_t)(kt + row) * 768 + n0 + nq);
            *(float4*)&Bs[row][nq] = v;
        }
        __syncthreads();
#pragma unroll
        for (int k = 0; k < 16; k++) {
            float4 a0 = *(const float4*)&As[k][mt * 8];
            float4 a1 = *(const float4*)&As[k][mt * 8 + 4];
            ulonglong2 bA = *(const ulonglong2*)&Bs[k][nt * 8];
            ulonglong2 bB = *(const ulonglong2*)&Bs[k][nt * 8 + 4];
            float av[8] = {a0.x, a0.y, a0.z, a0.w, a1.x, a1.y, a1.z, a1.w};
#pragma unroll
            for (int i = 0; i < 8; i++) {
                unsigned long long ad = dup2(av[i]);
                ffma2(acc[i][0], ad, bA.x);
                ffma2(acc[i][1], ad, bA.y);
                ffma2(acc[i][2], ad, bB.x);
                ffma2(acc[i][3], ad, bB.y);
            }
        }
        __syncthreads();
    }
#pragma unroll
    for (int i = 0; i < 8; i++) {
        float2 c0 = unpack2(acc[i][0]);
        float2 c1 = unpack2(acc[i][1]);
        float2 c2 = unpack2(acc[i][2]);
        float2 c3 = unpack2(acc[i][3]);
        size_t off = (size_t)(m0 + mt * 8 + i) * 768 + n0 + nt * 8;
        *(float4*)(g_xi + off)     = make_float4(c0.x, c0.y, c1.x, c1.y);
        *(float4*)(g_xi + off + 4) = make_float4(c2.x, c2.y, c3.x, c3.y);
    }
}

// ============================================================
// Kernel 2: persistent GRU recurrence
// 128 CTAs = 8 batch-groups x 16 col-groups. Wh slice lives in smem.
// ============================================================

// smem float offsets (HOFF is now plain k*8 — injective, 16B aligned)
#define OFF_W   0                      // [256][50]  (48 cols + 2 pad)
#define OFF_HT  12800                  // [256][8]
#define OFF_RED 14848                  // [384][18]
#define OFF_HG  21760                  // [8][48]
#define OFF_BH  22144                  // [48]
#define OFF_BIN 22192                  // [16]
#define SMEM_FLOATS 22208
#define SMEM_BYTES (SMEM_FLOATS * 4)

__device__ __forceinline__ int HOFF(int k) { return k * 8; }

__global__ __launch_bounds__(NT, 1)
void gru_rec_kernel(const float* __restrict__ c,
                    const float* __restrict__ Wh,
                    const float* __restrict__ bh,
                    const float* __restrict__ b_in,
                    float* __restrict__ ys,
                    float* __restrict__ finalc) {
    extern __shared__ float sm[];
    float* sW   = sm + OFF_W;
    float* sHT  = sm + OFF_HT;
    float* sRED = sm + OFF_RED;
    float* sHG  = sm + OFF_HG;
    float* sBH  = sm + OFF_BH;
    float* sBIN = sm + OFF_BIN;

    const int tid = threadIdx.x;
    const int cg = blockIdx.x & 15;   // col group 0..15
    const int bg = blockIdx.x >> 4;   // batch group 0..7

    // ---- load Wh slice into smem: smem col cc = g*16 + jl -> Wh col g*256 + cg*16 + jl ----
    for (int idx = tid; idx < 256 * 48; idx += NT) {
        int k = idx / 48;
        int cc = idx - k * 48;
        int g = cc >> 4;
        int jl = cc & 15;
        sW[k * 50 + cc] = __ldg(Wh + (size_t)k * 768 + g * 256 + cg * 16 + jl);
    }
    // biases
    if (tid < 48) {
        int g = tid >> 4, jl = tid & 15;
        sBH[tid] = __ldg(bh + g * 256 + cg * 16 + jl);
    }
    if (tid >= 64 && tid < 80) {
        int jl = tid - 64;
        sBIN[jl] = __ldg(b_in + cg * 16 + jl);
    }
    // initial h from c: sHT[k*8 + bi] = c[bg*8+bi][k]
    for (int idx = tid; idx < BPG * 256; idx += NT) {
        int bi = idx >> 8;
        int k = idx & 255;
        sHT[HOFF(k) + bi] = __ldg(c + (size_t)(bg * 8 + bi) * 256 + k);
    }
    __syncthreads();

    // phase-1 thread mapping
    const int cp = tid % 24;       // col pair: smem cols 2cp, 2cp+1
    const int kc = tid / 24;       // k chunk 0..15, 16 k each
    // gate thread mapping (tid < 128)
    const int b_l = tid >> 4;      // 0..7
    const int jl = tid & 15;
    const int b_glob = bg * 8 + (b_l & 7);
    const int j_glob = cg * 16 + jl;

    for (int t = 0; t < TT; t++) {
        // -- prefetch xi for gate threads --
        float xr = 0.f, xz = 0.f, xn = 0.f;
        if (tid < 128) {
            const float* xp = g_xi + (size_t)t * (BB * NG) + (size_t)b_glob * NG + j_glob;
            xr = __ldg(xp);
            xz = __ldg(xp + 256);
            xn = __ldg(xp + 512);
        }

        // -- phase 1: partial dot products (8 batches x 2 cols, 16 k) --
        unsigned long long a0[4], a1[4];
#pragma unroll
        for (int i = 0; i < 4; i++) { a0[i] = 0ULL; a1[i] = 0ULL; }
        {
            const int kbase = kc * 16;
#pragma unroll
            for (int kk = 0; kk < 16; kk++) {
                int k = kbase + kk;
                ulonglong2 u0 = *(const ulonglong2*)&sHT[HOFF(k)];
                ulonglong2 u1 = *(const ulonglong2*)&sHT[HOFF(k) + 4];
                float2 w = *(const float2*)&sW[k * 50 + 2 * cp];
                unsigned long long wa = dup2(w.x);
                unsigned long long wb = dup2(w.y);
                ffma2(a0[0], u0.x, wa); ffma2(a0[1], u0.y, wa);
                ffma2(a0[2], u1.x, wa); ffma2(a0[3], u1.y, wa);
                ffma2(a1[0], u0.x, wb); ffma2(a1[1], u0.y, wb);
                ffma2(a1[2], u1.x, wb); ffma2(a1[3], u1.y, wb);
            }
        }
        // write partials: red[tid][0..7] = col 2cp (b0..b7), [8..15] = col 2cp+1
        {
            float* rp = sRED + tid * 18;
            *(unsigned long long*)(rp + 0)  = a0[0];
            *(unsigned long long*)(rp + 2)  = a0[1];
            *(unsigned long long*)(rp + 4)  = a0[2];
            *(unsigned long long*)(rp + 6)  = a0[3];
            *(unsigned long long*)(rp + 8)  = a1[0];
            *(unsigned long long*)(rp + 10) = a1[1];
            *(unsigned long long*)(rp + 12) = a1[2];
            *(unsigned long long*)(rp + 14) = a1[3];
        }
        __syncthreads();

        // -- phase 2: reduce over 16 k-chunks; one output per thread --
        {
            int cc = tid % 48;
            int b = tid / 48;
            int cpr = cc >> 1;
            int e = (cc & 1) * 8 + b;
            float s = 0.f;
#pragma unroll
            for (int q = 0; q < 16; q++)
                s += sRED[(q * 24 + cpr) * 18 + e];
            sHG[b * 48 + cc] = s;
        }
        __syncthreads();

        // -- phase 3: gates + h_new (threads < 128) --
        if (tid < 128) {
            float hr = sHG[b_l * 48 + jl]       + sBH[jl];
            float hz = sHG[b_l * 48 + 16 + jl]  + sBH[16 + jl];
            float hn = sHG[b_l * 48 + 32 + jl]  + sBH[32 + jl];
            float h_old = sHT[HOFF(j_glob) + b_l];
            float r = sigmoid_ap(xr + hr);
            float z = sigmoid_ap(xz + hz);
            float n = tanh_ap(xn + sBIN[jl] + r * hn);
            float h_new = (1.0f - z) * n + z * h_old;

            ys[(size_t)t * (BB * HH) + (size_t)b_glob * HH + j_glob] = h_new;
            g_hT2[(t & 1) * (HH * BB) + j_glob * BB + b_glob] = h_new;
            if (t == TT - 1)
                finalc[(size_t)b_glob * HH + j_glob] = h_new;
        }
        __threadfence();
        __syncthreads();

        // -- phase 4: grid barrier --
        if (tid == 0) {
            atomicAdd(&g_bar[t], 1u);
            unsigned v;
            do {
                v = *((volatile unsigned*)&g_bar[t]);
            } while (v < NCTA);
            __threadfence();
        }
        __syncthreads();

        // -- phase 5: reload full h for our 8 batches (bypass L1) --
        if (t + 1 < TT) {
            const float* src = g_hT2 + (t & 1) * (HH * BB);
            for (int idx = tid; idx < 512; idx += NT) {
                int k = idx >> 1;
                int h4 = (idx & 1) * 4;
                float4 v = __ldcg((const float4*)(src + k * 64 + bg * 8 + h4));
                *(float4*)&sHT[HOFF(k) + h4] = v;
            }
            __syncthreads();
        }
    }
}

// ============================================================
extern "C" void kernel_launch(void* const* d_in, const int* in_sizes, int n_in,
                              void* d_out, int out_size) {
    const float* c    = (const float*)d_in[0];
    const float* xs   = (const float*)d_in[1];
    const float* Wi   = (const float*)d_in[2];
    const float* Wh   = (const float*)d_in[3];
    const float* bh   = (const float*)d_in[4];
    const float* b_in = (const float*)d_in[5];

    float* dmp;
    cudaGetSymbolAddress((void**)&dmp, g_dump);

    float* out = (float*)d_out;
    float* finalc;
    float* ys;
    const long long full = (long long)BB * HH + (long long)TT * BB * HH;
    if ((long long)out_size >= full) {
        finalc = out;            // tuple order: final_c first, then ys
        ys = out + BB * HH;
    } else if ((long long)out_size >= (long long)TT * BB * HH) {
        ys = out;                // only ys fits; final_c goes to sink
        finalc = dmp;
    } else {
        finalc = out;            // only final_c fits; ys goes to sink
        ys = dmp;
    }

    // raise dynamic smem limit for the recurrence kernel (idempotent)
    cudaFuncSetAttribute(gru_rec_kernel, cudaFuncAttributeMaxDynamicSharedMemorySize, SMEM_BYTES);

    // 0) zero barrier counters
    zero_bar_kernel<<<(TT + 255) / 256, 256>>>();
    // 1) xi = xs @ Wi
    dim3 ggrid(NG / 128, (TT * BB) / 128);
    gemm_xi_kernel<<<ggrid, 256>>>(xs, Wi);
    // 2) recurrence
    gru_rec_kernel<<<NCTA, NT, SMEM_BYTES>>>(c, Wh, bh, b_in, ys, finalc);
}

// round 5
// speedup vs baseline: 1.0461x; 1.0461x over previous
#include <cuda_runtime.h>
#include <cuda_bf16.h>
#include <cstdint>

// Problem dims
#define TT 2048
#define BB 64
#define FFD 256
#define HH 256
#define NG 768  // 3*H

// Recurrence config: 16 clusters x 8 CTAs, 256 threads
#define CSZ 8
#define NCTA 128
#define NT 256

// -------- device scratch --------
__device__ float g_xi[(size_t)TT * BB * NG];     // 2048*64*768
__device__ float g_dump[(size_t)TT * BB * HH];   // fallback ys sink

// -------- packed f32x2 helpers --------
__device__ __forceinline__ void ffma2(unsigned long long& d, unsigned long long a, unsigned long long b) {
    asm volatile("fma.rn.f32x2 %0, %1, %2, %0;" : "+l"(d) : "l"(a), "l"(b));
}
__device__ __forceinline__ void add2(unsigned long long& d, unsigned long long a) {
    asm volatile("add.rn.f32x2 %0, %0, %1;" : "+l"(d) : "l"(a));
}
__device__ __forceinline__ unsigned long long dup2(float a) {
    unsigned long long d;
    asm("mov.b64 %0, {%1, %1};" : "=l"(d) : "f"(a));
    return d;
}
__device__ __forceinline__ float2 unpack2(unsigned long long d) {
    float2 f;
    asm("mov.b64 {%0, %1}, %2;" : "=f"(f.x), "=f"(f.y) : "l"(d));
    return f;
}
__device__ __forceinline__ float tanh_ap(float x) {
    float y;
    asm("tanh.approx.f32 %0, %1;" : "=f"(y) : "f"(x));
    return y;
}
__device__ __forceinline__ float sigmoid_ap(float x) {
    return 0.5f * tanh_ap(0.5f * x) + 0.5f;
}
__device__ __forceinline__ uint32_t smem_u32(const void* p) {
    uint32_t a;
    asm("{ .reg .u64 t; cvta.to.shared.u64 t, %1; cvt.u32.u64 %0, t; }" : "=r"(a) : "l"(p));
    return a;
}

// ============================================================
// Kernel 1: xi = xs @ Wi   (M=131072, K=256, N=768) — FFMA2 tiled
// ============================================================
__global__ __launch_bounds__(256, 2) void gemm_xi_kernel(const float* __restrict__ A,
                                                         const float* __restrict__ W) {
    __shared__ float As[16][132];
    __shared__ float Bs[16][128];
    const int tid = threadIdx.x;
    const int m0 = blockIdx.y * 128;
    const int n0 = blockIdx.x * 128;
    const int nt = tid & 15;
    const int mt = tid >> 4;

    unsigned long long acc[8][4];
#pragma unroll
    for (int i = 0; i < 8; i++)
#pragma unroll
        for (int j = 0; j < 4; j++) acc[i][j] = 0ULL;

    for (int kt = 0; kt < 256; kt += 16) {
#pragma unroll
        for (int i = 0; i < 2; i++) {
            int f4 = tid + i * 256;
            int row = f4 >> 2;
            int kq = (f4 & 3) << 2;
            float4 v = *(const float4*)(A + (size_t)(m0 + row) * 256 + kt + kq);
            As[kq + 0][row] = v.x; As[kq + 1][row] = v.y;
            As[kq + 2][row] = v.z; As[kq + 3][row] = v.w;
        }
#pragma unroll
        for (int i = 0; i < 2; i++) {
            int f4 = tid + i * 256;
            int row = f4 >> 5;
            int nq = (f4 & 31) << 2;
            float4 v = *(const float4*)(W + (size_t)(kt + row) * 768 + n0 + nq);
            *(float4*)&Bs[row][nq] = v;
        }
        __syncthreads();
#pragma unroll
        for (int k = 0; k < 16; k++) {
            float4 a0 = *(const float4*)&As[k][mt * 8];
            float4 a1 = *(const float4*)&As[k][mt * 8 + 4];
            ulonglong2 bA = *(const ulonglong2*)&Bs[k][nt * 8];
            ulonglong2 bB = *(const ulonglong2*)&Bs[k][nt * 8 + 4];
            float av[8] = {a0.x, a0.y, a0.z, a0.w, a1.x, a1.y, a1.z, a1.w};
#pragma unroll
            for (int i = 0; i < 8; i++) {
                unsigned long long ad = dup2(av[i]);
                ffma2(acc[i][0], ad, bA.x);
                ffma2(acc[i][1], ad, bA.y);
                ffma2(acc[i][2], ad, bB.x);
                ffma2(acc[i][3], ad, bB.y);
            }
        }
        __syncthreads();
    }
#pragma unroll
    for (int i = 0; i < 8; i++) {
        float2 c0 = unpack2(acc[i][0]);
        float2 c1 = unpack2(acc[i][1]);
        float2 c2 = unpack2(acc[i][2]);
        float2 c3 = unpack2(acc[i][3]);
        size_t off = (size_t)(m0 + mt * 8 + i) * 768 + n0 + nt * 8;
        *(float4*)(g_xi + off)     = make_float4(c0.x, c0.y, c1.x, c1.y);
        *(float4*)(g_xi + off + 4) = make_float4(c2.x, c2.y, c3.x, c3.y);
    }
}

// ============================================================
// Kernel 2: clustered GRU recurrence
// cluster (8 CTAs) = 4 batches; rank = 32 j-cols (96 Wh cols in smem)
// h exchange via DSMEM (st.shared::cluster) + cluster.sync
// ============================================================

// smem float offsets
#define OFF_W   0        // [256][96]
#define OFF_HT  24576    // [2][256][4]  double-buffered h: [buf][k][b]
#define OFF_RED 26624    // [256 threads][36]  partials, [b][g0 g1 g2 pad] x4
#define SMEM_FLOATS 35840
#define SMEM_BYTES (SMEM_FLOATS * 4)   // 143360

__global__ __launch_bounds__(NT, 1) __cluster_dims__(CSZ, 1, 1)
void gru_rec_kernel(const float* __restrict__ c,
                    const float* __restrict__ Wh,
                    const float* __restrict__ bh,
                    const float* __restrict__ b_in,
                    float* __restrict__ ys,
                    float* __restrict__ finalc) {
    extern __shared__ float sm[];
    float* sW  = sm + OFF_W;
    float* sHT = sm + OFF_HT;
    float* sRED = sm + OFF_RED;

    const int tid = threadIdx.x;
    uint32_t rank;
    asm("mov.u32 %0, %%cluster_ctarank;" : "=r"(rank));
    const int cid = blockIdx.x >> 3;          // cluster id 0..15 (batches 4cid..+3)

    // ---- init: Wh slice -> smem. col c96 = g*32+jj -> Wh col g*256 + rank*32 + jj
    for (int idx = tid; idx < 256 * 96; idx += NT) {
        int k = idx / 96;
        int c96 = idx - k * 96;
        int g = c96 >> 5;
        int jj = c96 & 31;
        sW[k * 96 + c96] = __ldg(Wh + (size_t)k * 768 + g * 256 + (int)rank * 32 + jj);
    }
    // initial h into buf 0: sHT[0][k][b] = c[cid*4+b][k]
    for (int idx = tid; idx < 1024; idx += NT) {
        int k = idx >> 2;
        int b = idx & 3;
        sHT[k * 4 + b] = __ldg(c + (size_t)(cid * 4 + b) * 256 + k);
    }

    // phase-1 mapping
    const int kc = tid >> 4;       // k-chunk 0..15 (16 k each)
    const int jp = tid & 15;       // j-pair 0..15 -> j cols (2jp, 2jp+1) within rank slice

    // gate mapping (tid < 64): jp_g = tid&15, b_g = tid>>4
    const int jp_g = tid & 15;
    const int b_g = tid >> 4;
    const int j0 = (int)rank * 32 + jp_g * 2;      // global j (even)
    const int b_glob = cid * 4 + b_g;

    // gate-thread constants
    float2 bhr2 = make_float2(0.f, 0.f), bhz2 = bhr2, bhn2 = bhr2, bin2 = bhr2;
    if (tid < 64) {
        bhr2 = __ldg((const float2*)(bh + j0));
        bhz2 = __ldg((const float2*)(bh + 256 + j0));
        bhn2 = __ldg((const float2*)(bh + 512 + j0));
        bin2 = __ldg((const float2*)(b_in + j0));
    }

    // precompute remote sHT base addresses for all 8 ranks
    uint32_t ht_local = smem_u32(sHT);
    uint32_t rbase[CSZ];
#pragma unroll
    for (int r = 0; r < CSZ; r++) {
        asm("mapa.shared::cluster.u32 %0, %1, %2;" : "=r"(rbase[r]) : "r"(ht_local), "r"(r));
    }

    __syncthreads();
    // make sure every CTA's smem (incl. sHT buffers) is set up before any
    // peer DSMEM writes can land
    asm volatile("barrier.cluster.arrive.aligned;" ::: "memory");
    asm volatile("barrier.cluster.wait.aligned;" ::: "memory");

    int cur = 0;
    for (int t = 0; t < TT; t++) {
        const int nxt = cur ^ 1;

        // -- gate threads: prefetch xi early (DRAM latency hidden by phase 1) --
        float2 xr2, xz2, xn2;
        if (tid < 64) {
            const float* xp = g_xi + ((size_t)t * 64 + b_glob) * 768 + j0;
            xr2 = __ldg((const float2*)xp);
            xz2 = __ldg((const float2*)(xp + 256));
            xn2 = __ldg((const float2*)(xp + 512));
        }

        // -- phase 1: partial GEMV. acc[g][b] = f32x2 over (j0,j1) --
        unsigned long long acc[3][4];
#pragma unroll
        for (int g = 0; g < 3; g++)
#pragma unroll
            for (int b = 0; b < 4; b++) acc[g][b] = 0ULL;
        {
            const float* hb = sHT + cur * 1024;
            const int kbase = kc * 16;
#pragma unroll
            for (int kk = 0; kk < 16; kk++) {
                const int k = kbase + kk;
                float4 h4 = *(const float4*)(hb + k * 4);
                unsigned long long d0 = dup2(h4.x);
                unsigned long long d1 = dup2(h4.y);
                unsigned long long d2 = dup2(h4.z);
                unsigned long long d3 = dup2(h4.w);
                const float* wr = sW + k * 96 + jp * 2;
                unsigned long long w0 = *(const unsigned long long*)(wr);
                unsigned long long w1 = *(const unsigned long long*)(wr + 32);
                unsigned long long w2 = *(const unsigned long long*)(wr + 64);
                ffma2(acc[0][0], w0, d0); ffma2(acc[0][1], w0, d1);
                ffma2(acc[0][2], w0, d2); ffma2(acc[0][3], w0, d3);
                ffma2(acc[1][0], w1, d0); ffma2(acc[1][1], w1, d1);
                ffma2(acc[1][2], w1, d2); ffma2(acc[1][3], w1, d3);
                ffma2(acc[2][0], w2, d0); ffma2(acc[2][1], w2, d1);
                ffma2(acc[2][2], w2, d2); ffma2(acc[2][3], w2, d3);
            }
        }
        // write partials: [b][g0 g1 | g2 pad]
        {
            float* rp = sRED + tid * 36;
#pragma unroll
            for (int b = 0; b < 4; b++) {
                ulonglong2 v;
                v.x = acc[0][b];
                v.y = acc[1][b];
                *(ulonglong2*)(rp + b * 8) = v;
                *(unsigned long long*)(rp + b * 8 + 4) = acc[2][b];
            }
        }
        __syncthreads();

        // -- phase 2+3: reduce + gates + exchange (64 threads) --
        if (tid < 64) {
            unsigned long long r2 = 0ULL, z2 = 0ULL, n2 = 0ULL;
            const float* rp = sRED + jp_g * 36 + b_g * 8;
#pragma unroll
            for (int q = 0; q < 16; q++) {
                const float* p = rp + q * (16 * 36);
                ulonglong2 v = *(const ulonglong2*)p;
                unsigned long long v2 = *(const unsigned long long*)(p + 4);
                add2(r2, v.x);
                add2(z2, v.y);
                add2(n2, v2);
            }
            float2 hr = unpack2(r2), hz = unpack2(z2), hn = unpack2(n2);
            float ho0 = sHT[cur * 1024 + j0 * 4 + b_g];
            float ho1 = sHT[cur * 1024 + (j0 + 1) * 4 + b_g];

            float r0 = sigmoid_ap(xr2.x + hr.x + bhr2.x);
            float r1 = sigmoid_ap(xr2.y + hr.y + bhr2.y);
            float z0 = sigmoid_ap(xz2.x + hz.x + bhz2.x);
            float z1 = sigmoid_ap(xz2.y + hz.y + bhz2.y);
            float n0 = tanh_ap(xn2.x + bin2.x + r0 * (hn.x + bhn2.x));
            float n1 = tanh_ap(xn2.y + bin2.y + r1 * (hn.y + bhn2.y));
            float h_new0 = (1.0f - z0) * n0 + z0 * ho0;
            float h_new1 = (1.0f - z1) * n1 + z1 * ho1;

            // outputs
            *(float2*)&ys[((size_t)t * 64 + b_glob) * 256 + j0] = make_float2(h_new0, h_new1);
            if (t == TT - 1)
                *(float2*)&finalc[(size_t)b_glob * 256 + j0] = make_float2(h_new0, h_new1);

            // DSMEM broadcast into every rank's sHT[nxt][j][b]
            uint32_t off0 = (uint32_t)(nxt * 1024 + j0 * 4 + b_g) * 4u;
            uint32_t off1 = off0 + 16u;
#pragma unroll
            for (int r = 0; r < CSZ; r++) {
                asm volatile("st.shared::cluster.f32 [%0], %1;" :: "r"(rbase[r] + off0), "f"(h_new0) : "memory");
                asm volatile("st.shared::cluster.f32 [%0], %1;" :: "r"(rbase[r] + off1), "f"(h_new1) : "memory");
            }
        }

        // -- cluster barrier: h_new visible everywhere --
        asm volatile("barrier.cluster.arrive.aligned;" ::: "memory");
        asm volatile("barrier.cluster.wait.aligned;" ::: "memory");

        cur = nxt;
    }
}

// ============================================================
extern "C" void kernel_launch(void* const* d_in, const int* in_sizes, int n_in,
                              void* d_out, int out_size) {
    const float* c    = (const float*)d_in[0];
    const float* xs   = (const float*)d_in[1];
    const float* Wi   = (const float*)d_in[2];
    const float* Wh   = (const float*)d_in[3];
    const float* bh   = (const float*)d_in[4];
    const float* b_in = (const float*)d_in[5];

    float* dmp;
    cudaGetSymbolAddress((void**)&dmp, g_dump);

    float* out = (float*)d_out;
    float* finalc;
    float* ys;
    const long long full = (long long)BB * HH + (long long)TT * BB * HH;
    if ((long long)out_size >= full) {
        finalc = out;            // tuple order: final_c first, then ys
        ys = out + BB * HH;
    } else if ((long long)out_size >= (long long)TT * BB * HH) {
        ys = out;
        finalc = dmp;
    } else {
        finalc = out;
        ys = dmp;
    }

    cudaFuncSetAttribute(gru_rec_kernel, cudaFuncAttributeMaxDynamicSharedMemorySize, SMEM_BYTES);

    // 1) xi = xs @ Wi
    dim3 ggrid(NG / 128, (TT * BB) / 128);
    gemm_xi_kernel<<<ggrid, 256>>>(xs, Wi);
    // 2) clustered recurrence
    gru_rec_kernel<<<NCTA, NT, SMEM_BYTES>>>(c, Wh, bh, b_in, ys, finalc);
}